// round 1
// baseline (speedup 1.0000x reference)
#include <cuda_runtime.h>

#define SEQ       128
#define BATCH     512
#define INPUT_DIM 128
#define HIDDEN    128
#define NQ        8
#define QDIM      256   // 2^NQ

// Recurrent state carried across per-timestep kernels (no allocs allowed).
__device__ float g_h[BATCH * HIDDEN];
__device__ float g_c[BATCH * HIDDEN];

__global__ __launch_bounds__(128, 8)
void qlstm_step(const float* __restrict__ inputs,  // [SEQ,BATCH,INPUT_DIM]
                const float* __restrict__ Wq,      // [32, 256] (only rows 0..7 used)
                const float* __restrict__ bq,      // [32]
                const float* __restrict__ pf,      // [2,8]
                const float* __restrict__ pi_,
                const float* __restrict__ pg,
                const float* __restrict__ po,
                const float* __restrict__ Wf, const float* __restrict__ bf,
                const float* __restrict__ Wi, const float* __restrict__ bi,
                const float* __restrict__ Wg, const float* __restrict__ bg,
                const float* __restrict__ Wo, const float* __restrict__ bo,
                float* __restrict__ out, int t)
{
    const int b    = blockIdx.x;
    const int tid  = threadIdx.x;
    const int wid  = tid >> 5;
    const int lane = tid & 31;

    __shared__ float comb[256];
    __shared__ float qin[8];
    __shared__ float zsh[4][8];

    // ---- load combined = [x_t ; h_{t-1}] ----
    comb[tid]       = inputs[(size_t)t * BATCH * INPUT_DIM + (size_t)b * INPUT_DIM + tid];
    comb[128 + tid] = (t == 0) ? 0.f : g_h[b * HIDDEN + tid];
    __syncthreads();

    // ---- q_in = combined @ Wq[:8].T + bq[:8]  (warp wid -> rows 2*wid, 2*wid+1) ----
    {
        const float* w0 = Wq + (2 * wid) * 256;
        const float* w1 = Wq + (2 * wid + 1) * 256;
        float a0 = 0.f, a1 = 0.f;
        #pragma unroll
        for (int j = 0; j < 8; j++) {
            int idx = lane + 32 * j;
            float v = comb[idx];
            a0 = fmaf(v, __ldg(w0 + idx), a0);
            a1 = fmaf(v, __ldg(w1 + idx), a1);
        }
        #pragma unroll
        for (int o = 16; o; o >>= 1) {
            a0 += __shfl_xor_sync(0xffffffffu, a0, o);
            a1 += __shfl_xor_sync(0xffffffffu, a1, o);
        }
        if (lane == 0) {
            qin[2 * wid]     = a0 + __ldg(bq + 2 * wid);
            qin[2 * wid + 1] = a1 + __ldg(bq + 2 * wid + 1);
        }
    }
    __syncthreads();

    // ---- quantum circuit sim: one warp per gate (0:f 1:i 2:g 3:o) ----
    const float* params = (wid == 0) ? pf : (wid == 1) ? pi_ : (wid == 2) ? pg : po;

    float cw[NQ], sw[NQ];
    #pragma unroll
    for (int w = 0; w < NQ; w++) {
        float th = 0.5f * qin[w];
        cw[w] = cosf(th);
        sw[w] = sinf(th);
    }

    // Initial amplitudes after RX encoding: A0[k] = (prod mags) * (-i)^popc(k)
    // k = (lane<<3) | r.  Bit position p of k corresponds to wire (7-p).
    float ar[8], ai[8];
    float lm = 1.f;
    #pragma unroll
    for (int i = 0; i < 5; i++) {           // lane bits -> k bits 3..7 -> wires 4..0
        int w = 4 - i;
        lm *= ((lane >> i) & 1) ? sw[w] : cw[w];
    }
    #pragma unroll
    for (int r = 0; r < 8; r++) {
        float m = lm;
        #pragma unroll
        for (int i = 0; i < 3; i++) {        // local bits -> k bits 0..2 -> wires 7..5
            int w = 7 - i;
            m *= ((r >> i) & 1) ? sw[w] : cw[w];
        }
        int k  = (lane << 3) | r;
        int pc = __popc(k) & 3;              // (-i)^pc
        ar[r] = (pc == 0) ? m : ((pc == 2) ? -m : 0.f);
        ai[r] = (pc == 1) ? -m : ((pc == 3) ? m : 0.f);
    }

    // Two RY layers. CNOT chains are fused as the Gray map g(k)=k^(k>>1):
    //   layer d=0: logical == physical  -> pairMask = 1<<p, side = bit p of k
    //   layer d=1: logical l at phys g(l) -> pairMask = g(1<<p), side = popc(k & (0xFF<<p))&1
    #pragma unroll
    for (int d = 0; d < 2; d++) {
        #pragma unroll
        for (int w = 0; w < NQ; w++) {
            const int p = 7 - w;
            float th = 0.5f * __ldg(params + d * NQ + w);
            float rc = cosf(th), rs = sinf(th);
            const int pairMask = (d == 0) ? (1 << p) : ((p > 0) ? (3 << (p - 1)) : 1);
            const int sideMask = (d == 0) ? (1 << p) : ((0xFF << p) & 0xFF);
            const int laneXor  = pairMask >> 3;
            const int localXor = pairMask & 7;

            float pr[8], pim[8];
            #pragma unroll
            for (int r = 0; r < 8; r++) {
                float vr = ar[r ^ localXor];
                float vi = ai[r ^ localXor];
                if (laneXor) {
                    vr = __shfl_xor_sync(0xffffffffu, vr, laneXor);
                    vi = __shfl_xor_sync(0xffffffffu, vi, laneXor);
                }
                pr[r] = vr; pim[r] = vi;
            }
            #pragma unroll
            for (int r = 0; r < 8; r++) {
                int k = (lane << 3) | r;
                float sgn = (__popc(k & sideMask) & 1) ? rs : -rs;
                ar[r] = fmaf(sgn, pr[r],  rc * ar[r]);
                ai[r] = fmaf(sgn, pim[r], rc * ai[r]);
            }
        }
    }

    // ---- Z expectations: total basis map is g^2: k -> k^(k>>2); inverse bit p is
    //      parity of bits {p, p+2, p+4, p+6}: mask (0x55<<p)&0xFF ----
    float prob[8];
    #pragma unroll
    for (int r = 0; r < 8; r++) prob[r] = ar[r] * ar[r] + ai[r] * ai[r];

    #pragma unroll
    for (int p = 0; p < 8; p++) {
        const int mz = (0x55 << p) & 0xFF;
        float acc = 0.f;
        #pragma unroll
        for (int r = 0; r < 8; r++) {
            int k = (lane << 3) | r;
            acc += (__popc(k & mz) & 1) ? -prob[r] : prob[r];
        }
        #pragma unroll
        for (int o = 16; o; o >>= 1) acc += __shfl_xor_sync(0xffffffffu, acc, o);
        if (lane == 0) zsh[wid][7 - p] = acc;   // z for wire w = 7-p
    }
    __syncthreads();

    // ---- gate projections + LSTM update: thread tid handles hidden unit tid ----
    {
        const int h = tid;
        float accf = __ldg(bf + h), acci = __ldg(bi + h);
        float accg = __ldg(bg + h), acco = __ldg(bo + h);
        #pragma unroll
        for (int w = 0; w < NQ; w++) {
            accf = fmaf(zsh[0][w], __ldg(Wf + h * NQ + w), accf);
            acci = fmaf(zsh[1][w], __ldg(Wi + h * NQ + w), acci);
            accg = fmaf(zsh[2][w], __ldg(Wg + h * NQ + w), accg);
            acco = fmaf(zsh[3][w], __ldg(Wo + h * NQ + w), acco);
        }
        float fg = 1.f / (1.f + expf(-accf));
        float ig = 1.f / (1.f + expf(-acci));
        float gg = tanhf(accg);
        float og = 1.f / (1.f + expf(-acco));

        float cold = (t == 0) ? 0.f : g_c[b * HIDDEN + h];
        float cn = fmaf(fg, cold, ig * gg);
        float hn = og * tanhf(cn);

        g_c[b * HIDDEN + h] = cn;
        g_h[b * HIDDEN + h] = hn;

        out[(size_t)t * BATCH * HIDDEN + (size_t)b * HIDDEN + h] = hn;
        if (t == SEQ - 1) {
            size_t base = (size_t)SEQ * BATCH * HIDDEN;
            out[base + (size_t)b * HIDDEN + h] = hn;                      // hx
            out[base + (size_t)BATCH * HIDDEN + (size_t)b * HIDDEN + h] = cn;  // cx
        }
    }
}

extern "C" void kernel_launch(void* const* d_in, const int* in_sizes, int n_in,
                              void* d_out, int out_size)
{
    const float* inputs = (const float*)d_in[0];
    const float* Wq     = (const float*)d_in[1];
    const float* bq     = (const float*)d_in[2];
    const float* pf     = (const float*)d_in[3];
    const float* pi_    = (const float*)d_in[4];
    const float* pg     = (const float*)d_in[5];
    const float* po     = (const float*)d_in[6];
    const float* Wf     = (const float*)d_in[7];
    const float* bf     = (const float*)d_in[8];
    const float* Wi     = (const float*)d_in[9];
    const float* bi     = (const float*)d_in[10];
    const float* Wg     = (const float*)d_in[11];
    const float* bg     = (const float*)d_in[12];
    const float* Wo     = (const float*)d_in[13];
    const float* bo     = (const float*)d_in[14];
    float* out = (float*)d_out;

    for (int t = 0; t < SEQ; t++) {
        qlstm_step<<<BATCH, 128>>>(inputs, Wq, bq, pf, pi_, pg, po,
                                   Wf, bf, Wi, bi, Wg, bg, Wo, bo, out, t);
    }
}

// round 2
// speedup vs baseline: 2.7060x; 2.7060x over previous
#include <cuda_runtime.h>

#define SEQ       128
#define BATCH     512
#define INPUT_DIM 128
#define HIDDEN    128
#define NQ        8
#define NLAYERS   16   // DEPTH * NQ

__global__ __launch_bounds__(128, 4)
void qlstm_all(const float* __restrict__ inputs,  // [SEQ,BATCH,INPUT_DIM]
               const float* __restrict__ Wq,      // [32,256] rows 0..7 used
               const float* __restrict__ bq,      // [32]
               const float* __restrict__ pf,
               const float* __restrict__ pi_,
               const float* __restrict__ pg,
               const float* __restrict__ po,
               const float* __restrict__ Wf, const float* __restrict__ bf,
               const float* __restrict__ Wi, const float* __restrict__ bi,
               const float* __restrict__ Wg, const float* __restrict__ bg,
               const float* __restrict__ Wo, const float* __restrict__ bo,
               float* __restrict__ out)
{
    const int b    = blockIdx.x;
    const int tid  = threadIdx.x;
    const int wid  = tid >> 5;
    const int lane = tid & 31;

    __shared__ float sWq[8 * 256];        // 8KB
    __shared__ float sWg[4][HIDDEN * NQ]; // 16KB (f,i,g,o)
    __shared__ float sRc[4][NLAYERS];
    __shared__ float sRs[4][NLAYERS];
    __shared__ float sBq[8];
    __shared__ float comb[256];
    __shared__ float qin[8];
    __shared__ float zsh[4][8];

    // ---------- one-time setup ----------
    for (int i = tid; i < 8 * 256; i += 128) sWq[i] = Wq[i];
    for (int i = tid; i < HIDDEN * NQ; i += 128) {
        sWg[0][i] = Wf[i]; sWg[1][i] = Wi[i]; sWg[2][i] = Wg[i]; sWg[3][i] = Wo[i];
    }
    if (tid < 8) sBq[tid] = bq[tid];

    const float* params = (wid == 0) ? pf : (wid == 1) ? pi_ : (wid == 2) ? pg : po;
    if (lane < NLAYERS) {
        float th = 0.5f * params[lane];   // layer l = d*8+w, params flat [2,8]
        float c, s;
        __sincosf(th, &s, &c);
        sRc[wid][lane] = c;
        sRs[wid][lane] = s;
    }

    // per-thread LSTM constants (thread tid <-> hidden unit tid)
    const float bfr = bf[tid], bir = bi[tid], bgr = bg[tid], bor = bo[tid];

    float hreg = 0.f, creg = 0.f;
    __syncthreads();

    const float* inb = inputs + (size_t)b * INPUT_DIM;

    for (int t = 0; t < SEQ; t++) {
        // ---- combined = [x_t ; h_{t-1}] ----
        comb[tid]       = inb[(size_t)t * BATCH * INPUT_DIM + tid];
        comb[128 + tid] = hreg;
        __syncthreads();

        // ---- q_in = combined @ Wq[:8].T + bq[:8] ----
        {
            const float* w0 = sWq + (2 * wid) * 256;
            const float* w1 = sWq + (2 * wid + 1) * 256;
            float a0 = 0.f, a1 = 0.f;
            #pragma unroll
            for (int j = 0; j < 8; j++) {
                int idx = lane + 32 * j;
                float v = comb[idx];
                a0 = fmaf(v, w0[idx], a0);
                a1 = fmaf(v, w1[idx], a1);
            }
            #pragma unroll
            for (int o = 16; o; o >>= 1) {
                a0 += __shfl_xor_sync(0xffffffffu, a0, o);
                a1 += __shfl_xor_sync(0xffffffffu, a1, o);
            }
            if (lane == 0) {
                qin[2 * wid]     = a0 + sBq[2 * wid];
                qin[2 * wid + 1] = a1 + sBq[2 * wid + 1];
            }
        }
        __syncthreads();

        // ---- RX encoding: product state ----
        float cw[NQ], sw[NQ];
        #pragma unroll
        for (int w = 0; w < NQ; w++) {
            __sincosf(0.5f * qin[w], &sw[w], &cw[w]);
        }

        float ar[8], ai[8];
        float lm = 1.f;
        #pragma unroll
        for (int i = 0; i < 5; i++) {           // lane bits -> k bits 3..7 -> wires 4..0
            int w = 4 - i;
            lm *= ((lane >> i) & 1) ? sw[w] : cw[w];
        }
        #pragma unroll
        for (int r = 0; r < 8; r++) {
            float m = lm;
            #pragma unroll
            for (int i = 0; i < 3; i++) {        // local bits -> k bits 0..2 -> wires 7..5
                int w = 7 - i;
                m *= ((r >> i) & 1) ? sw[w] : cw[w];
            }
            int k  = (lane << 3) | r;
            int pc = __popc(k) & 3;              // (-i)^pc phase
            ar[r] = (pc == 0) ? m : ((pc == 2) ? -m : 0.f);
            ai[r] = (pc == 1) ? -m : ((pc == 3) ? m : 0.f);
        }

        // ---- 2 x (RY layer + fused CNOT chain as Gray remap) ----
        #pragma unroll
        for (int d = 0; d < 2; d++) {
            #pragma unroll
            for (int w = 0; w < NQ; w++) {
                const int p  = 7 - w;
                const float rc = sRc[wid][d * NQ + w];
                const float rs = sRs[wid][d * NQ + w];
                const int pairMask = (d == 0) ? (1 << p) : ((p > 0) ? (3 << (p - 1)) : 1);
                const int sideMask = (d == 0) ? (1 << p) : ((0xFF << p) & 0xFF);
                const int laneXor  = pairMask >> 3;
                const int localXor = pairMask & 7;

                float pr[8], pim[8];
                #pragma unroll
                for (int r = 0; r < 8; r++) {
                    float vr = ar[r ^ localXor];
                    float vi = ai[r ^ localXor];
                    if (laneXor) {
                        vr = __shfl_xor_sync(0xffffffffu, vr, laneXor);
                        vi = __shfl_xor_sync(0xffffffffu, vi, laneXor);
                    }
                    pr[r] = vr; pim[r] = vi;
                }
                #pragma unroll
                for (int r = 0; r < 8; r++) {
                    int k = (lane << 3) | r;
                    float sgn = (__popc(k & sideMask) & 1) ? rs : -rs;
                    ar[r] = fmaf(sgn, pr[r],  rc * ar[r]);
                    ai[r] = fmaf(sgn, pim[r], rc * ai[r]);
                }
            }
        }

        // ---- Z expectations. Basis map g^2: inverse-bit-p parity mask (0x55<<p)&0xFF.
        //      Sign factorizes: parity(lane & mz>>3) * parity(r & mz&7).
        //      mz&7 == 0 for p>=3 -> those reuse S = sum(prob). ----
        float prob[8];
        #pragma unroll
        for (int r = 0; r < 8; r++) prob[r] = ar[r] * ar[r] + ai[r] * ai[r];

        float S0 = 0.f, S1 = 0.f, S2 = 0.f, SA = 0.f;   // inner sums for mz&7 = 5,2,4,0
        #pragma unroll
        for (int r = 0; r < 8; r++) {
            float v = prob[r];
            SA += v;
            S0 += (__popc(r & 5) & 1) ? -v : v;
            S1 += (__popc(r & 2) & 1) ? -v : v;
            S2 += (__popc(r & 4) & 1) ? -v : v;
        }
        #pragma unroll
        for (int p = 0; p < 8; p++) {
            const int mz = (0x55 << p) & 0xFF;
            float base = (p == 0) ? S0 : (p == 1) ? S1 : (p == 2) ? S2 : SA;
            float acc = (__popc(lane & (mz >> 3)) & 1) ? -base : base;
            #pragma unroll
            for (int o = 16; o; o >>= 1) acc += __shfl_xor_sync(0xffffffffu, acc, o);
            if (lane == 0) zsh[wid][7 - p] = acc;   // z for wire w = 7-p
        }
        __syncthreads();

        // ---- gate projections + LSTM update ----
        {
            float accf = bfr, acci = bir, accg = bgr, acco = bor;
            const float* wf = sWg[0] + tid * NQ;
            const float* wi = sWg[1] + tid * NQ;
            const float* wg = sWg[2] + tid * NQ;
            const float* wo = sWg[3] + tid * NQ;
            #pragma unroll
            for (int w = 0; w < NQ; w++) {
                accf = fmaf(zsh[0][w], wf[w], accf);
                acci = fmaf(zsh[1][w], wi[w], acci);
                accg = fmaf(zsh[2][w], wg[w], accg);
                acco = fmaf(zsh[3][w], wo[w], acco);
            }
            float fg = 1.f / (1.f + __expf(-accf));
            float ig = 1.f / (1.f + __expf(-acci));
            float e2 = __expf(2.f * accg);
            float gg = (e2 - 1.f) / (e2 + 1.f);
            float og = 1.f / (1.f + __expf(-acco));

            creg = fmaf(fg, creg, ig * gg);
            float e2c = __expf(2.f * creg);
            hreg = og * (e2c - 1.f) / (e2c + 1.f);

            out[(size_t)t * BATCH * HIDDEN + (size_t)b * HIDDEN + tid] = hreg;
        }
        __syncthreads();   // protect comb/zsh before next iteration's writes
    }

    // ---- final hx, cx ----
    size_t base = (size_t)SEQ * BATCH * HIDDEN;
    out[base + (size_t)b * HIDDEN + tid] = hreg;
    out[base + (size_t)BATCH * HIDDEN + (size_t)b * HIDDEN + tid] = creg;
}

extern "C" void kernel_launch(void* const* d_in, const int* in_sizes, int n_in,
                              void* d_out, int out_size)
{
    const float* inputs = (const float*)d_in[0];
    const float* Wq     = (const float*)d_in[1];
    const float* bq     = (const float*)d_in[2];
    const float* pf     = (const float*)d_in[3];
    const float* pi_    = (const float*)d_in[4];
    const float* pg     = (const float*)d_in[5];
    const float* po     = (const float*)d_in[6];
    const float* Wf     = (const float*)d_in[7];
    const float* bf     = (const float*)d_in[8];
    const float* Wi     = (const float*)d_in[9];
    const float* bi     = (const float*)d_in[10];
    const float* Wg     = (const float*)d_in[11];
    const float* bg     = (const float*)d_in[12];
    const float* Wo     = (const float*)d_in[13];
    const float* bo     = (const float*)d_in[14];
    float* out = (float*)d_out;

    qlstm_all<<<BATCH, 128>>>(inputs, Wq, bq, pf, pi_, pg, po,
                              Wf, bf, Wi, bi, Wg, bg, Wo, bo, out);
}

// round 3
// speedup vs baseline: 3.6018x; 1.3310x over previous
#include <cuda_runtime.h>

#define SEQ       128
#define BATCH     512
#define INPUT_DIM 128
#define HIDDEN    128
#define NQ        8
#define NLAYERS   16   // DEPTH * NQ

typedef unsigned long long u64;

__device__ __forceinline__ u64 pk(float lo, float hi) {
    u64 r; asm("mov.b64 %0, {%1, %2};" : "=l"(r) : "f"(lo), "f"(hi)); return r;
}
__device__ __forceinline__ void upk(u64 v, float& lo, float& hi) {
    asm("mov.b64 {%0, %1}, %2;" : "=f"(lo), "=f"(hi) : "l"(v));
}
#define MUL2(o,a,b)   asm("mul.rn.f32x2 %0, %1, %2;"     : "=l"(o) : "l"(a), "l"(b))
#define FMA2(o,a,b,c) asm("fma.rn.f32x2 %0, %1, %2, %3;" : "=l"(o) : "l"(a), "l"(b), "l"(c))

__global__ __launch_bounds__(128, 4)
void qlstm_all(const float* __restrict__ inputs,  // [SEQ,BATCH,INPUT_DIM]
               const float* __restrict__ Wq,      // [32,256] rows 0..7 used
               const float* __restrict__ bq,      // [32]
               const float* __restrict__ pf,
               const float* __restrict__ pi_,
               const float* __restrict__ pg,
               const float* __restrict__ po,
               const float* __restrict__ Wf, const float* __restrict__ bf,
               const float* __restrict__ Wi, const float* __restrict__ bi,
               const float* __restrict__ Wg, const float* __restrict__ bg,
               const float* __restrict__ Wo, const float* __restrict__ bo,
               float* __restrict__ out)
{
    const int b    = blockIdx.x;
    const int tid  = threadIdx.x;
    const int wid  = tid >> 5;
    const int lane = tid & 31;

    __shared__ float sWq[8 * 256];          // 8KB
    __shared__ float sWgT[4][NQ][HIDDEN];   // 16KB, transposed: [gate][wire][hidden]
    __shared__ float sRc[4][NLAYERS];
    __shared__ float sRs[4][NLAYERS];
    __shared__ float sBq[8];
    __shared__ float comb[2][256];          // double-buffered
    __shared__ float qin[2][8];
    __shared__ float zsh[2][4][8];

    // ---------- one-time setup ----------
    for (int i = tid; i < 8 * 256; i += 128) sWq[i] = Wq[i];
    for (int i = tid; i < HIDDEN * NQ; i += 128) {
        int h = i >> 3, w = i & 7;
        sWgT[0][w][h] = Wf[i]; sWgT[1][w][h] = Wi[i];
        sWgT[2][w][h] = Wg[i]; sWgT[3][w][h] = Wo[i];
    }
    if (tid < 8) sBq[tid] = bq[tid];

    const float* params = (wid == 0) ? pf : (wid == 1) ? pi_ : (wid == 2) ? pg : po;
    if (lane < NLAYERS) {
        float c, s;
        __sincosf(0.5f * params[lane], &s, &c);
        sRc[wid][lane] = c;
        sRs[wid][lane] = s;
    }

    const float bfr = bf[tid], bir = bi[tid], bgr = bg[tid], bor = bo[tid];

    float hreg = 0.f, creg = 0.f;
    const float* inb = inputs + (size_t)b * INPUT_DIM;
    float xcur = inb[tid];                 // prefetch t=0
    __syncthreads();

    for (int t = 0; t < SEQ; t++) {
        const int buf = t & 1;

        comb[buf][tid]       = xcur;
        comb[buf][128 + tid] = hreg;
        float xnext = 0.f;
        if (t + 1 < SEQ) xnext = inb[(size_t)(t + 1) * BATCH * INPUT_DIM + tid];
        __syncthreads();   // A: comb visible

        // ---- q_in = combined @ Wq[:8].T + bq[:8] (warp wid -> rows 2wid, 2wid+1) ----
        {
            const float* w0 = sWq + (2 * wid) * 256;
            const float* w1 = sWq + (2 * wid + 1) * 256;
            float a0 = 0.f, a1 = 0.f;
            #pragma unroll
            for (int j = 0; j < 8; j++) {
                int idx = lane + 32 * j;
                float v = comb[buf][idx];
                a0 = fmaf(v, w0[idx], a0);
                a1 = fmaf(v, w1[idx], a1);
            }
            #pragma unroll
            for (int o = 16; o; o >>= 1) {
                a0 += __shfl_xor_sync(0xffffffffu, a0, o);
                a1 += __shfl_xor_sync(0xffffffffu, a1, o);
            }
            if (lane == 0) {
                qin[buf][2 * wid]     = a0 + sBq[2 * wid];
                qin[buf][2 * wid + 1] = a1 + sBq[2 * wid + 1];
            }
        }
        __syncthreads();   // B: qin visible

        // ---- RX encoding: product state ----
        float cw[NQ], sw[NQ];
        #pragma unroll
        for (int w = 0; w < NQ; w++)
            __sincosf(0.5f * qin[buf][w], &sw[w], &cw[w]);

        u64 st[8];   // packed (re, im) amplitudes, k = (lane<<3)|r
        {
            float lm = 1.f;
            #pragma unroll
            for (int i = 0; i < 5; i++) {          // lane bits -> k bits 3..7 -> wires 4..0
                int w = 4 - i;
                lm *= ((lane >> i) & 1) ? sw[w] : cw[w];
            }
            #pragma unroll
            for (int r = 0; r < 8; r++) {
                float m = lm;
                #pragma unroll
                for (int i = 0; i < 3; i++) {      // local bits -> k bits 0..2 -> wires 7..5
                    int w = 7 - i;
                    m *= ((r >> i) & 1) ? sw[w] : cw[w];
                }
                int k  = (lane << 3) | r;
                int pc = __popc(k) & 3;            // (-i)^pc phase
                float re = (pc == 0) ? m : ((pc == 2) ? -m : 0.f);
                float im = (pc == 1) ? -m : ((pc == 3) ? m : 0.f);
                st[r] = pk(re, im);
            }
        }

        // ---- 2 x (RY layer + fused CNOT chain as Gray remap), packed f32x2 ----
        #pragma unroll
        for (int d = 0; d < 2; d++) {
            #pragma unroll
            for (int w = 0; w < NQ; w++) {
                const int p  = 7 - w;
                const float rc = sRc[wid][d * NQ + w];
                const float rs = sRs[wid][d * NQ + w];
                const int pairMask = (d == 0) ? (1 << p) : ((p > 0) ? (3 << (p - 1)) : 1);
                const int sideMask = (d == 0) ? (1 << p) : ((0xFF << p) & 0xFF);
                const int laneXor  = pairMask >> 3;
                const int localXor = pairMask & 7;
                const int laneSide = (sideMask >> 3) & 31;
                const int rSide    = sideMask & 7;

                // lane-dependent sign (same for all r), r-dependent sign is compile-time
                float base = (__popc(lane & laneSide) & 1) ? rs : -rs;
                u64 rc2 = pk(rc, rc);
                u64 bp  = pk(base, base);
                u64 bn  = pk(-base, -base);

                u64 prt[8];
                #pragma unroll
                for (int r = 0; r < 8; r++) {
                    u64 v = st[r ^ localXor];
                    if (laneXor) v = __shfl_xor_sync(0xffffffffu, v, laneXor);
                    prt[r] = v;
                }
                #pragma unroll
                for (int r = 0; r < 8; r++) {
                    const int pir = __popc(r & rSide) & 1;   // compile-time
                    u64 coef = pir ? bn : bp;
                    u64 tmp;
                    MUL2(tmp, rc2, st[r]);
                    FMA2(st[r], coef, prt[r], tmp);
                }
            }
        }

        // ---- Z expectations via Walsh-Hadamard over lanes ----
        float prob[8];
        #pragma unroll
        for (int r = 0; r < 8; r++) {
            float re, im;
            upk(st[r], re, im);
            prob[r] = fmaf(re, re, im * im);
        }

        // local 3-bit Walsh tree: masks 0 (SA), 2 (S1), 4 (S2), 5 (S0)
        float u0 = prob[0] + prob[4], v0 = prob[0] - prob[4];
        float u1 = prob[1] + prob[5], v1 = prob[1] - prob[5];
        float u2 = prob[2] + prob[6], v2 = prob[2] - prob[6];
        float u3 = prob[3] + prob[7], v3 = prob[3] - prob[7];
        float SA = (u0 + u1) + (u2 + u3);            // mask 0
        float S1 = (u0 + u1) - (u2 + u3);            // mask 2 (bit1)
        float S2 = (v0 + v1) + (v2 + v3);            // mask 4 (bit2)
        float S0 = (v0 - v1) + (v2 - v3);            // mask 5 (bits 0,2)

        // 5-level signed butterflies: lane m ends with Walsh coeff of mask m
        #pragma unroll
        for (int i = 0; i < 5; i++) {
            const int o = 1 << i;
            float pA = __shfl_xor_sync(0xffffffffu, SA, o);
            float p0 = __shfl_xor_sync(0xffffffffu, S0, o);
            float p1 = __shfl_xor_sync(0xffffffffu, S1, o);
            float p2 = __shfl_xor_sync(0xffffffffu, S2, o);
            if ((lane >> i) & 1) {
                SA = pA - SA; S0 = p0 - S0; S1 = p1 - S1; S2 = p2 - S2;
            } else {
                SA = SA + pA; S0 = S0 + p0; S1 = S1 + p1; S2 = S2 + p2;
            }
        }
        // z[wire 7-p]: p=0..2 from S0/S1/S2, p=3..7 from SA; lane = (0x55<<p)>>3 & 0xFF>>3
        if (lane == 0x0A) { zsh[buf][wid][7] = S0; zsh[buf][wid][5] = S2; zsh[buf][wid][3] = SA; }
        if (lane == 0x15) { zsh[buf][wid][6] = S1; zsh[buf][wid][4] = SA; }
        if (lane == 0x14) zsh[buf][wid][2] = SA;
        if (lane == 0x08) zsh[buf][wid][1] = SA;
        if (lane == 0x10) zsh[buf][wid][0] = SA;
        __syncthreads();   // C: zsh visible

        // ---- gate projections + LSTM update (thread tid <-> hidden unit tid) ----
        {
            float accf = bfr, acci = bir, accg = bgr, acco = bor;
            #pragma unroll
            for (int w = 0; w < NQ; w++) {
                accf = fmaf(zsh[buf][0][w], sWgT[0][w][tid], accf);
                acci = fmaf(zsh[buf][1][w], sWgT[1][w][tid], acci);
                accg = fmaf(zsh[buf][2][w], sWgT[2][w][tid], accg);
                acco = fmaf(zsh[buf][3][w], sWgT[3][w][tid], acco);
            }
            float fg = __fdividef(1.f, 1.f + __expf(-accf));
            float ig = __fdividef(1.f, 1.f + __expf(-acci));
            float e2 = __expf(2.f * accg);
            float gg = __fdividef(e2 - 1.f, e2 + 1.f);
            float og = __fdividef(1.f, 1.f + __expf(-acco));

            creg = fmaf(fg, creg, ig * gg);
            float e2c = __expf(2.f * creg);
            hreg = og * __fdividef(e2c - 1.f, e2c + 1.f);

            out[(size_t)t * BATCH * HIDDEN + (size_t)b * HIDDEN + tid] = hreg;
        }
        xcur = xnext;
        // no tail sync: next iteration uses the other buffer
    }

    // ---- final hx, cx ----
    size_t base = (size_t)SEQ * BATCH * HIDDEN;
    out[base + (size_t)b * HIDDEN + tid] = hreg;
    out[base + (size_t)BATCH * HIDDEN + (size_t)b * HIDDEN + tid] = creg;
}

extern "C" void kernel_launch(void* const* d_in, const int* in_sizes, int n_in,
                              void* d_out, int out_size)
{
    const float* inputs = (const float*)d_in[0];
    const float* Wq     = (const float*)d_in[1];
    const float* bq     = (const float*)d_in[2];
    const float* pf     = (const float*)d_in[3];
    const float* pi_    = (const float*)d_in[4];
    const float* pg     = (const float*)d_in[5];
    const float* po     = (const float*)d_in[6];
    const float* Wf     = (const float*)d_in[7];
    const float* bf     = (const float*)d_in[8];
    const float* Wi     = (const float*)d_in[9];
    const float* bi     = (const float*)d_in[10];
    const float* Wg     = (const float*)d_in[11];
    const float* bg     = (const float*)d_in[12];
    const float* Wo     = (const float*)d_in[13];
    const float* bo     = (const float*)d_in[14];
    float* out = (float*)d_out;

    qlstm_all<<<BATCH, 128>>>(inputs, Wq, bq, pf, pi_, pg, po,
                              Wf, bf, Wi, bi, Wg, bg, Wo, bo, out);
}

// round 4
// speedup vs baseline: 4.8886x; 1.3573x over previous
#include <cuda_runtime.h>

#define SEQ       128
#define BATCH     512
#define INPUT_DIM 128
#define HIDDEN    128
#define NQ        8
#define NLAYERS   16   // DEPTH * NQ

typedef unsigned long long u64;

__device__ __forceinline__ u64 pk(float lo, float hi) {
    u64 r; asm("mov.b64 %0, {%1, %2};" : "=l"(r) : "f"(lo), "f"(hi)); return r;
}
__device__ __forceinline__ void upk(u64 v, float& lo, float& hi) {
    asm("mov.b64 {%0, %1}, %2;" : "=f"(lo), "=f"(hi) : "l"(v));
}
#define MUL2(o,a,b)   asm("mul.rn.f32x2 %0, %1, %2;"     : "=l"(o) : "l"(a), "l"(b))
#define FMA2(o,a,b,c) asm("fma.rn.f32x2 %0, %1, %2, %3;" : "=l"(o) : "l"(a), "l"(b), "l"(c))

// complex multiply (scalar): (or,oi) = (ar,ai)*(br,bi)
__device__ __forceinline__ void cmul(float& orr, float& oi,
                                     float ar, float ai, float br, float bi) {
    orr = fmaf(ar, br, -ai * bi);
    oi  = fmaf(ar, bi,  ai * br);
}

__global__ __launch_bounds__(128, 4)
void qlstm_all(const float* __restrict__ inputs,  // [SEQ,BATCH,INPUT_DIM]
               const float* __restrict__ Wq,      // [32,256] rows 0..7 used
               const float* __restrict__ bq,      // [32]
               const float* __restrict__ pf,
               const float* __restrict__ pi_,
               const float* __restrict__ pg,
               const float* __restrict__ po,
               const float* __restrict__ Wf, const float* __restrict__ bf,
               const float* __restrict__ Wi, const float* __restrict__ bi,
               const float* __restrict__ Wg, const float* __restrict__ bg,
               const float* __restrict__ Wo, const float* __restrict__ bo,
               float* __restrict__ out)
{
    const int b    = blockIdx.x;
    const int tid  = threadIdx.x;
    const int wid  = tid >> 5;
    const int lane = tid & 31;

    __shared__ float sWq[8 * 256];          // 8KB
    __shared__ float sWgT[4][NQ][HIDDEN];   // 16KB, transposed: [gate][wire][hidden]
    __shared__ float sC0[4][NQ], sS0[4][NQ];   // d0 RY constants (folded into init)
    __shared__ float sRc[4][NQ], sRs[4][NQ];   // d1 RY constants
    __shared__ float sBq[8];
    __shared__ float comb[2][256];          // double-buffered
    __shared__ float qin[2][8];
    __shared__ float zsh[2][4][8];

    // ---------- one-time setup ----------
    for (int i = tid; i < 8 * 256; i += 128) sWq[i] = Wq[i];
    for (int i = tid; i < HIDDEN * NQ; i += 128) {
        int h = i >> 3, w = i & 7;
        sWgT[0][w][h] = Wf[i]; sWgT[1][w][h] = Wi[i];
        sWgT[2][w][h] = Wg[i]; sWgT[3][w][h] = Wo[i];
    }
    if (tid < 8) sBq[tid] = bq[tid];

    const float* params = (wid == 0) ? pf : (wid == 1) ? pi_ : (wid == 2) ? pg : po;
    if (lane < NLAYERS) {
        float c, s;
        __sincosf(0.5f * params[lane], &s, &c);
        if (lane < NQ) { sC0[wid][lane] = c;      sS0[wid][lane] = s;      }
        else           { sRc[wid][lane - NQ] = c; sRs[wid][lane - NQ] = s; }
    }

    const float bfr = bf[tid], bir = bi[tid], bgr = bg[tid], bor = bo[tid];

    float hreg = 0.f, creg = 0.f;
    const float* inb = inputs + (size_t)b * INPUT_DIM;
    float xcur = inb[tid];                 // prefetch t=0
    __syncthreads();

    for (int t = 0; t < SEQ; t++) {
        const int buf = t & 1;

        comb[buf][tid]       = xcur;
        comb[buf][128 + tid] = hreg;
        float xnext = 0.f;
        if (t + 1 < SEQ) xnext = inb[(size_t)(t + 1) * BATCH * INPUT_DIM + tid];
        __syncthreads();   // A: comb visible

        // ---- q_in = combined @ Wq[:8].T + bq[:8] (warp wid -> rows 2wid, 2wid+1) ----
        {
            const float* w0 = sWq + (2 * wid) * 256;
            const float* w1 = sWq + (2 * wid + 1) * 256;
            float a0 = 0.f, a1 = 0.f;
            #pragma unroll
            for (int j = 0; j < 8; j++) {
                int idx = lane + 32 * j;
                float v = comb[buf][idx];
                a0 = fmaf(v, w0[idx], a0);
                a1 = fmaf(v, w1[idx], a1);
            }
            #pragma unroll
            for (int o = 16; o; o >>= 1) {
                a0 += __shfl_xor_sync(0xffffffffu, a0, o);
                a1 += __shfl_xor_sync(0xffffffffu, a1, o);
            }
            if (lane == 0) {
                qin[buf][2 * wid]     = a0 + sBq[2 * wid];
                qin[buf][2 * wid + 1] = a1 + sBq[2 * wid + 1];
            }
        }
        __syncthreads();   // B: qin visible

        // ---- init: product state after RX + first RY layer (folded) ----
        // per-wire column of RY(phi)*RX(theta) applied to |0>:
        //   A_w = (cf*ct,  sf*st)   (amplitude for bit 0)
        //   B_w = (sf*ct, -cf*st)   (amplitude for bit 1)
        float Are[NQ], Aim[NQ], Bre[NQ], Bim[NQ];
        #pragma unroll
        for (int w = 0; w < NQ; w++) {
            float st_, ct_;
            __sincosf(0.5f * qin[buf][w], &st_, &ct_);
            float cf = sC0[wid][w], sf = sS0[wid][w];
            Are[w] = cf * ct_;  Aim[w] = sf * st_;
            Bre[w] = sf * ct_;  Bim[w] = -cf * st_;
        }

        // lane product over wires 4..0  (lane bit i <-> k bit 3+i <-> wire 4-i)
        float Lr, Li;
        {
            int s0 = lane & 1;
            Lr = s0 ? Bre[4] : Are[4];
            Li = s0 ? Bim[4] : Aim[4];
            #pragma unroll
            for (int i = 1; i < 5; i++) {
                int w = 4 - i;
                int s = (lane >> i) & 1;
                float xr = s ? Bre[w] : Are[w];
                float xi = s ? Bim[w] : Aim[w];
                float nr, ni;
                cmul(nr, ni, Lr, Li, xr, xi);
                Lr = nr; Li = ni;
            }
        }

        // register tree over wires 7,6,5 (k bits 0,1,2)
        float Tr[4], Ti[4];           // u7 x u6
        #pragma unroll
        for (int j = 0; j < 4; j++) {
            float xr = (j & 1) ? Bre[7] : Are[7];
            float xi = (j & 1) ? Bim[7] : Aim[7];
            float yr = (j & 2) ? Bre[6] : Are[6];
            float yi = (j & 2) ? Bim[6] : Aim[6];
            cmul(Tr[j], Ti[j], xr, xi, yr, yi);
        }

        u64 st[8];   // packed (re, im), k = (lane<<3) | r
        #pragma unroll
        for (int r = 0; r < 8; r++) {
            float ur = (r & 4) ? Bre[5] : Are[5];
            float ui = (r & 4) ? Bim[5] : Aim[5];
            float Rr, Ri;
            cmul(Rr, Ri, Tr[r & 3], Ti[r & 3], ur, ui);
            float fr, fi;
            cmul(fr, fi, Lr, Li, Rr, Ri);
            st[r] = pk(fr, fi);
        }

        // ---- second RY layer (CNOT chains fused as Gray remap), packed f32x2 ----
        #pragma unroll
        for (int w = 0; w < NQ; w++) {
            const int p  = 7 - w;
            const float rc = sRc[wid][w];
            const float rs = sRs[wid][w];
            const int pairMask = (p > 0) ? (3 << (p - 1)) : 1;
            const int sideMask = (0xFF << p) & 0xFF;
            const int laneXor  = pairMask >> 3;
            const int localXor = pairMask & 7;
            const int laneSide = (sideMask >> 3) & 31;
            const int rSide    = sideMask & 7;

            float base = (__popc(lane & laneSide) & 1) ? rs : -rs;
            u64 rc2 = pk(rc, rc);
            u64 bp  = pk(base, base);
            u64 bn  = pk(-base, -base);

            u64 prt[8];
            #pragma unroll
            for (int r = 0; r < 8; r++) {
                u64 v = st[r ^ localXor];
                if (laneXor) v = __shfl_xor_sync(0xffffffffu, v, laneXor);
                prt[r] = v;
            }
            #pragma unroll
            for (int r = 0; r < 8; r++) {
                const int pir = __popc(r & rSide) & 1;   // compile-time
                u64 coef = pir ? bn : bp;
                u64 tmp;
                MUL2(tmp, rc2, st[r]);
                FMA2(st[r], coef, prt[r], tmp);
            }
        }

        // ---- Z expectations via Walsh-Hadamard over lanes ----
        float prob[8];
        #pragma unroll
        for (int r = 0; r < 8; r++) {
            float re, im;
            upk(st[r], re, im);
            prob[r] = fmaf(re, re, im * im);
        }

        // local 3-bit Walsh tree: masks 0 (SA), 2 (S1), 4 (S2), 5 (S0)
        float u0 = prob[0] + prob[4], v0 = prob[0] - prob[4];
        float u1 = prob[1] + prob[5], v1 = prob[1] - prob[5];
        float u2 = prob[2] + prob[6], v2 = prob[2] - prob[6];
        float u3 = prob[3] + prob[7], v3 = prob[3] - prob[7];
        float SA = (u0 + u1) + (u2 + u3);            // mask 0
        float S1 = (u0 + u1) - (u2 + u3);            // mask 2 (bit1)
        float S2 = (v0 + v1) + (v2 + v3);            // mask 4 (bit2)
        float S0 = (v0 - v1) + (v2 - v3);            // mask 5 (bits 0,2)

        #pragma unroll
        for (int i = 0; i < 5; i++) {
            const int o = 1 << i;
            float pA = __shfl_xor_sync(0xffffffffu, SA, o);
            float p0 = __shfl_xor_sync(0xffffffffu, S0, o);
            float p1 = __shfl_xor_sync(0xffffffffu, S1, o);
            float p2 = __shfl_xor_sync(0xffffffffu, S2, o);
            if ((lane >> i) & 1) {
                SA = pA - SA; S0 = p0 - S0; S1 = p1 - S1; S2 = p2 - S2;
            } else {
                SA = SA + pA; S0 = S0 + p0; S1 = S1 + p1; S2 = S2 + p2;
            }
        }
        // z[wire 7-p]: p=0..2 from S0/S1/S2, p=3..7 from SA
        if (lane == 0x0A) { zsh[buf][wid][7] = S0; zsh[buf][wid][5] = S2; zsh[buf][wid][3] = SA; }
        if (lane == 0x15) { zsh[buf][wid][6] = S1; zsh[buf][wid][4] = SA; }
        if (lane == 0x14) zsh[buf][wid][2] = SA;
        if (lane == 0x08) zsh[buf][wid][1] = SA;
        if (lane == 0x10) zsh[buf][wid][0] = SA;
        __syncthreads();   // C: zsh visible

        // ---- gate projections + LSTM update (thread tid <-> hidden unit tid) ----
        {
            float accf = bfr, acci = bir, accg = bgr, acco = bor;
            #pragma unroll
            for (int w = 0; w < NQ; w++) {
                accf = fmaf(zsh[buf][0][w], sWgT[0][w][tid], accf);
                acci = fmaf(zsh[buf][1][w], sWgT[1][w][tid], acci);
                accg = fmaf(zsh[buf][2][w], sWgT[2][w][tid], accg);
                acco = fmaf(zsh[buf][3][w], sWgT[3][w][tid], acco);
            }
            float fg = __fdividef(1.f, 1.f + __expf(-accf));
            float ig = __fdividef(1.f, 1.f + __expf(-acci));
            float e2 = __expf(2.f * accg);
            float gg = __fdividef(e2 - 1.f, e2 + 1.f);
            float og = __fdividef(1.f, 1.f + __expf(-acco));

            creg = fmaf(fg, creg, ig * gg);
            float e2c = __expf(2.f * creg);
            hreg = og * __fdividef(e2c - 1.f, e2c + 1.f);

            out[(size_t)t * BATCH * HIDDEN + (size_t)b * HIDDEN + tid] = hreg;
        }
        xcur = xnext;
        // no tail sync: next iteration uses the other buffer
    }

    // ---- final hx, cx ----
    size_t base = (size_t)SEQ * BATCH * HIDDEN;
    out[base + (size_t)b * HIDDEN + tid] = hreg;
    out[base + (size_t)BATCH * HIDDEN + (size_t)b * HIDDEN + tid] = creg;
}

extern "C" void kernel_launch(void* const* d_in, const int* in_sizes, int n_in,
                              void* d_out, int out_size)
{
    const float* inputs = (const float*)d_in[0];
    const float* Wq     = (const float*)d_in[1];
    const float* bq     = (const float*)d_in[2];
    const float* pf     = (const float*)d_in[3];
    const float* pi_    = (const float*)d_in[4];
    const float* pg     = (const float*)d_in[5];
    const float* po     = (const float*)d_in[6];
    const float* Wf     = (const float*)d_in[7];
    const float* bf     = (const float*)d_in[8];
    const float* Wi     = (const float*)d_in[9];
    const float* bi     = (const float*)d_in[10];
    const float* Wg     = (const float*)d_in[11];
    const float* bg     = (const float*)d_in[12];
    const float* Wo     = (const float*)d_in[13];
    const float* bo     = (const float*)d_in[14];
    float* out = (float*)d_out;

    qlstm_all<<<BATCH, 128>>>(inputs, Wq, bq, pf, pi_, pg, po,
                              Wf, bf, Wi, bi, Wg, bg, Wo, bo, out);
}